// round 13
// baseline (speedup 1.0000x reference)
#include <cuda_runtime.h>

// B=8192, D=512, NUM_CLASSES=90, K=8
// Numerics (validated R9-R12): per dot, NEON VF4xIC2 structure:
//   8 independent serial FMA chains, chain j covers elements 8i+j (i=0..63);
//   combine v_e = fadd(chain_e, chain_{e+4}); dot = fadd(fadd(v0,v1),fadd(v2,v3));
//   d = fadd(1,dot). Epilogue f32 per-op rounded, k ascending. Batch sums double.
// R13: R10 geometry (1440x128, CPAD=520 conflict-free) + barrier-free loop
// (x from GMEM via coalescer dedup) + S=2 sample interleave (c LDS amortized 2x).

#define NUM_CLASSES 90
#define CHUNKS      16
#define CHUNK_B     512
#define NBLK        (NUM_CLASSES * CHUNKS)   // 1440
#define THREADS     128
#define NWARPS      4
#define CPAD        520    // 8k+4h mod 32 distinct per quarter-warp -> conflict-free

__device__ double   g_partials[NBLK];
__device__ unsigned g_count = 0;

__global__ __launch_bounds__(THREADS) void loss_main(
    const float* __restrict__ x,
    const float* __restrict__ centers,
    const int* __restrict__ labels,
    float* __restrict__ out)
{
    __shared__ float    cs[8 * CPAD];
    __shared__ int      list[CHUNK_B];
    __shared__ unsigned gmask[16];
    __shared__ int      gbase[16];
    __shared__ int      s_n;
    __shared__ double   red[NWARPS];
    __shared__ int      s_last;

    const int tid    = threadIdx.x;
    const int cls    = blockIdx.x / CHUNKS;
    const int chunk  = blockIdx.x % CHUNKS;
    const int base_b = chunk * CHUNK_B;
    const int warp   = tid >> 5;
    const int lane   = tid & 31;

    // ---- stage this class's 8 center rows into padded SMEM (coalesced) ----
    const float4* __restrict__ gc4 =
        reinterpret_cast<const float4*>(centers + (size_t)cls * 8 * 512);
    for (int u = tid; u < 1024; u += THREADS) {
        int row = u >> 7, f4 = u & 127;
        float4 v = gc4[row * 128 + f4];
        *reinterpret_cast<float4*>(&cs[row * CPAD + f4 * 4]) = v;
    }

    // ---- deterministic scan: samples in this 512-chunk with label==cls ----
#pragma unroll
    for (int q = 0; q < 4; ++q) {
        int g = warp * 4 + q;
        int idx = base_b + g * 32 + lane;
        unsigned bal = __ballot_sync(0xFFFFFFFFu, labels[idx] == cls);
        if (lane == 0) gmask[g] = bal;
    }
    __syncthreads();
    if (warp == 0 && lane < 16) {
        int cnt = __popc(gmask[lane]);
        int inc = cnt;
#pragma unroll
        for (int off = 1; off < 16; off <<= 1) {
            int o = __shfl_up_sync(0x0000FFFFu, inc, off);
            if (lane >= off) inc += o;
        }
        gbase[lane] = inc - cnt;
        if (lane == 15) s_n = inc;
    }
    __syncthreads();
#pragma unroll
    for (int q = 0; q < 4; ++q) {
        int g = warp * 4 + q;
        unsigned m = gmask[g];
        if ((m >> lane) & 1u)
            list[gbase[g] + __popc(m & ((1u << lane) - 1u))] = g * 32 + lane;
    }
    __syncthreads();

    const int n = s_n;

    // lane roles within warp: 2 groups of 16 lanes; each group runs S=2 samples
    const int group = lane >> 4;            // 0/1
    const int g_id  = (warp << 1) | group;  // block-wide group id 0..7
    const int k     = (lane >> 1) & 7;
    const int h     = lane & 1;             // 0: chains 8i+0..3, 1: 8i+4..7
    const int gl    = lane & 16;            // leader lane of my 16-lane group

    const float* cb = &cs[k * CPAD + h * 4];
    double bsum = 0.0;

    // warp-uniform loop; groups own samples {2*g_id + 16r, 2*g_id+1 + 16r}
    for (int r = 0; 16 * r + 4 * warp < n; ++r) {
        const int si0 = 16 * r + 2 * g_id;
        const int si1 = si0 + 1;
        const bool a0 = (si0 < n);
        const bool a1 = (si1 < n);
        const int b0 = base_b + list[a0 ? si0 : 0];
        const int b1 = base_b + list[a1 ? si1 : 0];

        const float4* __restrict__ xg0 =
            reinterpret_cast<const float4*>(x + (size_t)b0 * 512);
        const float4* __restrict__ xg1 =
            reinterpret_cast<const float4*>(x + (size_t)b1 * 512);

        // two interleaved serial packet chains (exact validated order each)
        float4 acc0 = make_float4(0.f, 0.f, 0.f, 0.f);
        float4 acc1 = make_float4(0.f, 0.f, 0.f, 0.f);
#pragma unroll 8
        for (int i = 0; i < 64; ++i) {
            float4 cv = *reinterpret_cast<const float4*>(cb + i * 8); // 1 LDS / 2 samples
            float4 x0 = xg0[2 * i + h];   // 16B sector, dedup across 8 k-lanes
            float4 x1 = xg1[2 * i + h];
            acc0.x = fmaf(x0.x, cv.x, acc0.x);
            acc0.y = fmaf(x0.y, cv.y, acc0.y);
            acc0.z = fmaf(x0.z, cv.z, acc0.z);
            acc0.w = fmaf(x0.w, cv.w, acc0.w);
            acc1.x = fmaf(x1.x, cv.x, acc1.x);
            acc1.y = fmaf(x1.y, cv.y, acc1.y);
            acc1.z = fmaf(x1.z, cv.z, acc1.z);
            acc1.w = fmaf(x1.w, cv.w, acc1.w);
        }

        // combine partner chains (h^1); fadd bitwise-commutative
        float d0, d1;
        {
            float px = __shfl_xor_sync(0xFFFFFFFFu, acc0.x, 1);
            float py = __shfl_xor_sync(0xFFFFFFFFu, acc0.y, 1);
            float pz = __shfl_xor_sync(0xFFFFFFFFu, acc0.z, 1);
            float pw = __shfl_xor_sync(0xFFFFFFFFu, acc0.w, 1);
            float v0 = __fadd_rn(acc0.x, px);
            float v1 = __fadd_rn(acc0.y, py);
            float v2 = __fadd_rn(acc0.z, pz);
            float v3 = __fadd_rn(acc0.w, pw);
            d0 = __fadd_rn(1.0f, __fadd_rn(__fadd_rn(v0, v1), __fadd_rn(v2, v3)));
        }
        {
            float px = __shfl_xor_sync(0xFFFFFFFFu, acc1.x, 1);
            float py = __shfl_xor_sync(0xFFFFFFFFu, acc1.y, 1);
            float pz = __shfl_xor_sync(0xFFFFFFFFu, acc1.z, 1);
            float pw = __shfl_xor_sync(0xFFFFFFFFu, acc1.w, 1);
            float v0 = __fadd_rn(acc1.x, px);
            float v1 = __fadd_rn(acc1.y, py);
            float v2 = __fadd_rn(acc1.z, pz);
            float v3 = __fadd_rn(acc1.w, pw);
            d1 = __fadd_rn(1.0f, __fadd_rn(__fadd_rn(v0, v1), __fadd_rn(v2, v3)));
        }

        // gather 8 d_k per sample from even lanes of my group, run f32 epilogue
        float dl0[8], dl1[8];
#pragma unroll
        for (int j = 0; j < 8; ++j) {
            dl0[j] = __shfl_sync(0xFFFFFFFFu, d0, gl + 2 * j);
            dl1[j] = __shfl_sync(0xFFFFFFFFu, d1, gl + 2 * j);
        }
        float s1a = dl0[0], s1b = dl1[0];
#pragma unroll
        for (int j = 1; j < 8; ++j) {
            s1a = __fadd_rn(s1a, dl0[j]);
            s1b = __fadd_rn(s1b, dl1[j]);
        }
        float wa = 0.f, wb = 0.f;
#pragma unroll
        for (int j = 0; j < 8; ++j) {
            wa = __fadd_rn(wa, __fmul_rn(__fdiv_rn(dl0[j], s1a), dl0[j]));
            wb = __fadd_rn(wb, __fmul_rn(__fdiv_rn(dl1[j], s1b), dl1[j]));
        }
        if ((lane & 15) == 0) {
            if (a0) bsum += (double)wa;
            if (a1) bsum += (double)wb;
        }
    }

    // ---- deterministic block reduction (double) ----
#pragma unroll
    for (int m = 16; m >= 1; m >>= 1)
        bsum += __shfl_xor_sync(0xFFFFFFFFu, bsum, m);
    if (lane == 0) red[warp] = bsum;
    __syncthreads();
    if (tid == 0) {
        double t = 0.0;
#pragma unroll
        for (int j = 0; j < NWARPS; ++j) t += red[j];
        g_partials[blockIdx.x] = t;
        __threadfence();
        unsigned old = atomicInc(&g_count, NBLK - 1);   // wraps -> auto reset
        s_last = (old == NBLK - 1);
    }
    __syncthreads();

    // ---- last block folds all partials (fixed order -> deterministic) ----
    if (s_last) {
        double v = 0.0;
        for (int i = tid; i < NBLK; i += THREADS)
            v += __ldcg(&g_partials[i]);
#pragma unroll
        for (int m = 16; m >= 1; m >>= 1)
            v += __shfl_xor_sync(0xFFFFFFFFu, v, m);
        if (lane == 0) red[warp] = v;
        __syncthreads();
        if (tid == 0) {
            double t = 0.0;
#pragma unroll
            for (int j = 0; j < NWARPS; ++j) t += red[j];
            out[0] = (float)(t * (1.0 / 8192.0));
        }
    }
}

extern "C" void kernel_launch(void* const* d_in, const int* in_sizes, int n_in,
                              void* d_out, int out_size)
{
    const float* x       = (const float*)d_in[0];
    const float* centers = (const float*)d_in[1];
    const int*   labels  = (const int*)d_in[2];
    float*       out     = (float*)d_out;

    loss_main<<<NBLK, THREADS>>>(x, centers, labels, out);
}